// round 14
// baseline (speedup 1.0000x reference)
#include <cuda_runtime.h>
#include <cuda_bf16.h>
#include <cstdint>

// ---------------- scratch (device globals: allocation-free) ----------------
#define MB   8192
#define K1D  1024
#define HD   4096
#define OD   10
#define FIXCAP 1024
#define TAU  5e-4f

__device__ int8_t        g_S1i[(size_t)HD * K1D];      // sign(W1) s8
__device__ int8_t        g_S2i[(size_t)HD * HD];       // sign(W2) s8
__device__ int8_t        g_S3i[(size_t)OD * HD];       // sign(W3) s8
__device__ int8_t        g_A8x[(size_t)MB * 3 * K1D];  // x as 3 int8 digit planes
__device__ int8_t        g_A8[(size_t)MB * HD];        // +/-1 activations (s8)
__device__ float         g_lin[(size_t)MB * HD];       // L1 float out; L2/L3 s16 view
__device__ float         g_fS[HD];                     // L1 col sum (fp32 atomics)
__device__ float         g_fQ[HD];                     // L1 col sumsq
__device__ float         g_mean[HD];
__device__ float         g_inv [HD];
__device__ int           g_colFlag[HD];
__device__ int           g_list[FIXCAP];
__device__ int           g_fixCount[1];
__device__ float         g_fix[(size_t)MB * FIXCAP];   // exact outputs for flagged columns
__device__ int                g_isum[HD];
__device__ unsigned long long g_isq [HD];

// ---------------- weight binarization (s8) ----------------
__global__ void prep_w_s8(const float* __restrict__ W, int8_t* __restrict__ S, int I) {
    int o = blockIdx.x;
    const float* w = W + (size_t)o * I;
    __shared__ float red[256];
    float s = 0.f;
    for (int i = threadIdx.x; i < I; i += 256) s += fabsf(w[i]);
    red[threadIdx.x] = s; __syncthreads();
    for (int k = 128; k > 0; k >>= 1) {
        if (threadIdx.x < k) red[threadIdx.x] += red[threadIdx.x + k];
        __syncthreads();
    }
    int mask = (red[0] != 0.f) ? 1 : 0;
    for (int i = threadIdx.x; i < I; i += 256) {
        float v = w[i];
        int sg = (v > 0.f) ? 1 : ((v < 0.f) ? -1 : 0);
        S[(size_t)o * I + i] = (int8_t)(sg * mask);
    }
}

// ---------------- exact 3-plane int8 fixed-point split of x ----------------
__global__ void quant_x(const float* __restrict__ x, int8_t* __restrict__ Aq, int total) {
    int idx = blockIdx.x * 256 + threadIdx.x;
    if (idx >= total) return;
    int r = idx / K1D, k = idx % K1D;
    float v = x[idx];
    float d0 = rintf(v * 16.f);
    float r1 = v - d0 * 0.0625f;
    float d1 = rintf(r1 * 2048.f);
    float r2 = r1 - d1 * 4.8828125e-4f;
    float d2 = rintf(r2 * 262144.f);
    size_t base = (size_t)r * (3 * K1D) + k;
    Aq[base]            = (int8_t)(int)d0;
    Aq[base + K1D]      = (int8_t)(int)d1;
    Aq[base + 2 * K1D]  = (int8_t)(int)d2;
}

// ---------------- PTX helpers ----------------
static __device__ __forceinline__ uint32_t smem_u32(const void* p) {
    return (uint32_t)__cvta_generic_to_shared(p);
}
static __device__ __forceinline__ void cp_async16p(void* smem, const void* gmem, bool pred) {
    uint32_t s = smem_u32(smem);
    int sz = pred ? 16 : 0;
    asm volatile("cp.async.cg.shared.global [%0], [%1], 16, %2;\n" :: "r"(s), "l"(gmem), "r"(sz));
}
static __device__ __forceinline__ void ldsm_x4(uint32_t& r0, uint32_t& r1, uint32_t& r2,
                                               uint32_t& r3, uint32_t addr) {
    asm volatile("ldmatrix.sync.aligned.m8n8.x4.shared.b16 {%0,%1,%2,%3}, [%4];\n"
                 : "=r"(r0), "=r"(r1), "=r"(r2), "=r"(r3) : "r"(addr));
}
static __device__ __forceinline__ void mma_s8(int* c, uint32_t a0, uint32_t a1, uint32_t a2,
                                              uint32_t a3, uint32_t b0, uint32_t b1) {
    asm volatile("mma.sync.aligned.m16n8k32.row.col.s32.s8.s8.s32 "
                 "{%0,%1,%2,%3}, {%4,%5,%6,%7}, {%8,%9}, {%0,%1,%2,%3};\n"
                 : "+r"(c[0]), "+r"(c[1]), "+r"(c[2]), "+r"(c[3])
                 : "r"(a0), "r"(a1), "r"(a2), "r"(a3), "r"(b0), "r"(b1));
}

// ================= s8 IMMA GEMM common tile config ================
#define IBM 128
#define IBN 128
#define IBK 64
#define STAGES 4
#define ISAST 80
#define ISTG (IBM * ISAST)
#define ISMEM_BYTES (STAGES * 2 * ISTG)

// ====== s8 IMMA GEMM (layers 2, 3): raw s16 acc out + fused exact int col-stats ======
__global__ __launch_bounds__(256) void gemm_s8(
    const int8_t* __restrict__ A, const int8_t* __restrict__ B,
    int16_t* __restrict__ C16, int* __restrict__ gS, unsigned long long* __restrict__ gQ,
    int M, int N, int K, int ldc)
{
    extern __shared__ __align__(16) char smem_raw[];
    char* sA = smem_raw;
    char* sB = smem_raw + STAGES * ISTG;

    int tid = threadIdx.x;
    int mBase = blockIdx.y * IBM;
    int nBase = blockIdx.x * IBN;
    int warp = tid >> 5, lane = tid & 31;
    int wMB = (warp & 1) * 64;
    int wNB = (warp >> 1) * 32;
    int q = lane >> 2;

    int aRow = ((lane >> 3) & 1) * 8 + (lane & 7);
    int aCol = (lane >> 4) * 16;
    int bRow = (lane >> 4) * 8 + (lane & 7);
    int bCol = ((lane >> 3) & 1) * 16;

    int acc[4][4][4];
    #pragma unroll
    for (int i = 0; i < 4; i++)
        #pragma unroll
        for (int j = 0; j < 4; j++)
            #pragma unroll
            for (int r = 0; r < 4; r++) acc[i][j][r] = 0;

    int ktiles = K / IBK;

    #pragma unroll
    for (int st = 0; st < STAGES - 1; st++) {
        int k0 = st * IBK;
        #pragma unroll
        for (int i = 0; i < 2; i++) {
            int id = tid + i * 256;
            int r = id >> 2, c = id & 3;
            cp_async16p(sA + st * ISTG + r * ISAST + c * 16,
                        A + (size_t)(mBase + r) * K + k0 + c * 16, true);
            bool pb = (nBase + r) < N;
            cp_async16p(sB + st * ISTG + r * ISAST + c * 16,
                        B + (size_t)(nBase + r) * K + k0 + c * 16, pb);
        }
        asm volatile("cp.async.commit_group;\n");
    }

    for (int kt = 0; kt < ktiles; kt++) {
        asm volatile("cp.async.wait_group %0;\n" :: "n"(STAGES - 2));
        __syncthreads();

        int nt = kt + STAGES - 1;
        if (nt < ktiles) {
            int st = nt % STAGES;
            int k0 = nt * IBK;
            #pragma unroll
            for (int i = 0; i < 2; i++) {
                int id = tid + i * 256;
                int r = id >> 2, c = id & 3;
                cp_async16p(sA + st * ISTG + r * ISAST + c * 16,
                            A + (size_t)(mBase + r) * K + k0 + c * 16, true);
                bool pb = (nBase + r) < N;
                cp_async16p(sB + st * ISTG + r * ISAST + c * 16,
                            B + (size_t)(nBase + r) * K + k0 + c * 16, pb);
            }
        }
        asm volatile("cp.async.commit_group;\n");

        int stage = kt % STAGES;
        const char* tA = sA + stage * ISTG;
        const char* tB = sB + stage * ISTG;

        #pragma unroll
        for (int kk = 0; kk < 2; kk++) {
            int kb = kk * 32;
            uint32_t af[4][4], bf[4][2];
            #pragma unroll
            for (int im = 0; im < 4; im++) {
                uint32_t addr = smem_u32(tA + (wMB + im * 16 + aRow) * ISAST + kb + aCol);
                ldsm_x4(af[im][0], af[im][1], af[im][2], af[im][3], addr);
            }
            #pragma unroll
            for (int p = 0; p < 2; p++) {
                uint32_t addr = smem_u32(tB + (wNB + p * 16 + bRow) * ISAST + kb + bCol);
                uint32_t r0, r1, r2, r3;
                ldsm_x4(r0, r1, r2, r3, addr);
                bf[2 * p][0] = r0; bf[2 * p][1] = r1;
                bf[2 * p + 1][0] = r2; bf[2 * p + 1][1] = r3;
            }
            #pragma unroll
            for (int im = 0; im < 4; im++)
                #pragma unroll
                for (int jn = 0; jn < 4; jn++)
                    mma_s8(acc[im][jn], af[im][0], af[im][1], af[im][2], af[im][3],
                           bf[jn][0], bf[jn][1]);
        }
    }

    // ---- store raw s16 acc ----
    #pragma unroll
    for (int im = 0; im < 4; im++) {
        int mrow = mBase + wMB + im * 16 + q;
        #pragma unroll
        for (int jn = 0; jn < 4; jn++) {
            int ncol = nBase + wNB + jn * 8 + (lane & 3) * 2;
            #pragma unroll
            for (int rg = 0; rg < 2; rg++) {
                int row = mrow + rg * 8;
                if (ncol < N) {
                    short2 v;
                    v.x = (short)acc[im][jn][rg * 2 + 0];
                    v.y = (short)acc[im][jn][rg * 2 + 1];
                    *(short2*)&C16[(size_t)row * ldc + ncol] = v;
                }
            }
        }
    }

    // ---- fused exact integer column stats (deterministic: integer atomics) ----
    __syncthreads();
    int* sS = (int*)smem_raw;
    unsigned long long* sQ = (unsigned long long*)(smem_raw + 512);
    for (int i = tid; i < 128; i += 256) { sS[i] = 0; sQ[i] = 0ull; }
    __syncthreads();
    #pragma unroll
    for (int jn = 0; jn < 4; jn++) {
        int cl = wNB + jn * 8 + (lane & 3) * 2;
        int s0 = 0, s1 = 0; int q0 = 0, q1 = 0;
        #pragma unroll
        for (int im = 0; im < 4; im++)
            #pragma unroll
            for (int rg = 0; rg < 2; rg++) {
                int v0 = acc[im][jn][rg * 2 + 0];
                int v1 = acc[im][jn][rg * 2 + 1];
                s0 += v0; q0 += v0 * v0;
                s1 += v1; q1 += v1 * v1;
            }
        atomicAdd(&sS[cl], s0);
        atomicAdd(&sQ[cl], (unsigned long long)(long long)q0);
        atomicAdd(&sS[cl + 1], s1);
        atomicAdd(&sQ[cl + 1], (unsigned long long)(long long)q1);
    }
    __syncthreads();
    for (int c = tid; c < 128; c += 256) {
        if (nBase + c < N) {
            atomicAdd(&gS[nBase + c], sS[c]);
            atomicAdd(&gQ[nBase + c], sQ[c]);
        }
    }
}

// ====== s8 IMMA GEMM, layer 1: 3 digit planes + fused fp32 col stats ======
#define L1BN 64
#define L1BSTG (L1BN * ISAST)
#define L1STG (ISTG + L1BSTG)
#define L1SMEM_BYTES (STAGES * L1STG)
#define L1TILES 48    // 3 planes * (K1D/IBK)

__global__ __launch_bounds__(256, 2) void gemm_s8_l1(
    const int8_t* __restrict__ A, const int8_t* __restrict__ B,
    float* __restrict__ C, const float* __restrict__ bias, int ldc,
    float* __restrict__ fS, float* __restrict__ fQ)
{
    extern __shared__ __align__(16) char smem_raw[];
    char* sA = smem_raw;
    char* sB = smem_raw + STAGES * ISTG;

    int tid = threadIdx.x;
    int mBase = blockIdx.y * IBM;
    int nBase = blockIdx.x * L1BN;
    int warp = tid >> 5, lane = tid & 31;
    int wMB = (warp & 3) * 32;
    int wNB = (warp >> 2) * 32;
    int q = lane >> 2;

    int aRow = ((lane >> 3) & 1) * 8 + (lane & 7);
    int aCol = (lane >> 4) * 16;
    int bRow = (lane >> 4) * 8 + (lane & 7);
    int bCol = ((lane >> 3) & 1) * 16;

    const float scl[3] = {0.0625f, 4.8828125e-4f, 3.814697265625e-6f};

    int acc[2][4][4];
    float facc[2][4][4];
    #pragma unroll
    for (int i = 0; i < 2; i++)
        #pragma unroll
        for (int j = 0; j < 4; j++)
            #pragma unroll
            for (int r = 0; r < 4; r++) { acc[i][j][r] = 0; facc[i][j][r] = 0.f; }

    #pragma unroll
    for (int st = 0; st < STAGES - 1; st++) {
        int ka = st * IBK;
        int kb = (st & 15) * IBK;
        #pragma unroll
        for (int i = 0; i < 2; i++) {
            int id = tid + i * 256;
            int r = id >> 2, c = id & 3;
            cp_async16p(sA + st * ISTG + r * ISAST + c * 16,
                        A + (size_t)(mBase + r) * (3 * K1D) + ka + c * 16, true);
        }
        {
            int r = tid >> 2, c = tid & 3;
            cp_async16p(sB + st * L1BSTG + r * ISAST + c * 16,
                        B + (size_t)(nBase + r) * K1D + kb + c * 16, true);
        }
        asm volatile("cp.async.commit_group;\n");
    }

    for (int kt = 0; kt < L1TILES; kt++) {
        asm volatile("cp.async.wait_group %0;\n" :: "n"(STAGES - 2));
        __syncthreads();

        int nt = kt + STAGES - 1;
        if (nt < L1TILES) {
            int st = nt % STAGES;
            int ka = nt * IBK;
            int kb = (nt & 15) * IBK;
            #pragma unroll
            for (int i = 0; i < 2; i++) {
                int id = tid + i * 256;
                int r = id >> 2, c = id & 3;
                cp_async16p(sA + st * ISTG + r * ISAST + c * 16,
                            A + (size_t)(mBase + r) * (3 * K1D) + ka + c * 16, true);
            }
            {
                int r = tid >> 2, c = tid & 3;
                cp_async16p(sB + st * L1BSTG + r * ISAST + c * 16,
                            B + (size_t)(nBase + r) * K1D + kb + c * 16, true);
            }
        }
        asm volatile("cp.async.commit_group;\n");

        int stage = kt % STAGES;
        const char* tA = sA + stage * ISTG;
        const char* tB = sB + stage * L1BSTG;

        #pragma unroll
        for (int kk = 0; kk < 2; kk++) {
            int kb = kk * 32;
            uint32_t af[2][4], bf[4][2];
            #pragma unroll
            for (int im = 0; im < 2; im++) {
                uint32_t addr = smem_u32(tA + (wMB + im * 16 + aRow) * ISAST + kb + aCol);
                ldsm_x4(af[im][0], af[im][1], af[im][2], af[im][3], addr);
            }
            #pragma unroll
            for (int p = 0; p < 2; p++) {
                uint32_t addr = smem_u32(tB + (wNB + p * 16 + bRow) * ISAST + kb + bCol);
                uint32_t r0, r1, r2, r3;
                ldsm_x4(r0, r1, r2, r3, addr);
                bf[2 * p][0] = r0; bf[2 * p][1] = r1;
                bf[2 * p + 1][0] = r2; bf[2 * p + 1][1] = r3;
            }
            #pragma unroll
            for (int im = 0; im < 2; im++)
                #pragma unroll
                for (int jn = 0; jn < 4; jn++)
                    mma_s8(acc[im][jn], af[im][0], af[im][1], af[im][2], af[im][3],
                           bf[jn][0], bf[jn][1]);
        }

        if ((kt & 15) == 15) {
            float s = scl[kt >> 4];
            #pragma unroll
            for (int im = 0; im < 2; im++)
                #pragma unroll
                for (int jn = 0; jn < 4; jn++)
                    #pragma unroll
                    for (int r = 0; r < 4; r++) {
                        facc[im][jn][r] = fmaf(s, (float)acc[im][jn][r], facc[im][jn][r]);
                        acc[im][jn][r] = 0;
                    }
        }
    }

    // epilogue: write C and gather per-column fp32 stats
    float vout[2][4][4];
    #pragma unroll
    for (int im = 0; im < 2; im++) {
        int mrow = mBase + wMB + im * 16 + q;
        #pragma unroll
        for (int jn = 0; jn < 4; jn++) {
            int ncol = nBase + wNB + jn * 8 + (lane & 3) * 2;
            #pragma unroll
            for (int rg = 0; rg < 2; rg++) {
                int row = mrow + rg * 8;
                float v0 = facc[im][jn][rg * 2 + 0] + bias[ncol];
                float v1 = facc[im][jn][rg * 2 + 1] + bias[ncol + 1];
                vout[im][jn][rg * 2 + 0] = v0;
                vout[im][jn][rg * 2 + 1] = v1;
                C[(size_t)row * ldc + ncol]     = v0;
                C[(size_t)row * ldc + ncol + 1] = v1;
            }
        }
    }
    __syncthreads();
    float* sS = (float*)smem_raw;           // [64]
    float* sQ = sS + 64;                    // [64]
    for (int i = tid; i < 64; i += 256) { sS[i] = 0.f; sQ[i] = 0.f; }
    __syncthreads();
    #pragma unroll
    for (int jn = 0; jn < 4; jn++) {
        int cl = wNB + jn * 8 + (lane & 3) * 2;
        float s0 = 0.f, s1 = 0.f, q0 = 0.f, q1 = 0.f;
        #pragma unroll
        for (int im = 0; im < 2; im++)
            #pragma unroll
            for (int rg = 0; rg < 2; rg++) {
                float v0 = vout[im][jn][rg * 2 + 0];
                float v1 = vout[im][jn][rg * 2 + 1];
                s0 += v0; q0 = fmaf(v0, v0, q0);
                s1 += v1; q1 = fmaf(v1, v1, q1);
            }
        atomicAdd(&sS[cl], s0); atomicAdd(&sQ[cl], q0);
        atomicAdd(&sS[cl + 1], s1); atomicAdd(&sQ[cl + 1], q1);
    }
    __syncthreads();
    for (int c = tid; c < 64; c += 256) {
        atomicAdd(&fS[nBase + c], sS[c]);
        atomicAdd(&fQ[nBase + c], sQ[c]);
    }
}

// ---------------- L1 stats finalize ----------------
__global__ void clear_f(float* a, float* b, int n) {
    int i = blockIdx.x * 256 + threadIdx.x;
    if (i < n) { a[i] = 0.f; b[i] = 0.f; }
}
__global__ void l1_reduce(const float* __restrict__ fS, const float* __restrict__ fQ,
                          float* __restrict__ meanO, float* __restrict__ invO) {
    int c = blockIdx.x * 256 + threadIdx.x;
    float mu = fS[c] * (1.f / MB);
    float var = fmaxf(fQ[c] * (1.f / MB) - mu * mu, 0.f);
    meanO[c] = mu;
    invO[c] = rsqrtf(var + 1e-5f);
}

// ---------------- approx sign (s8 out) + boundary-column flagging, float4 ----------------
__global__ void clear_flags(int* __restrict__ flag, int* __restrict__ cnt) {
    int i = blockIdx.x * 256 + threadIdx.x;
    if (i < HD) flag[i] = 0;
    if (i == 0) cnt[0] = 0;
}
__global__ void bn_sign_flag(const float* __restrict__ X, int8_t* __restrict__ A,
                             const float* __restrict__ meanI, const float* __restrict__ invI,
                             const float* __restrict__ gamma, const float* __restrict__ beta,
                             int* __restrict__ flag) {
    int idx = blockIdx.x * 256 + threadIdx.x;
    int base = idx * 4;
    int c = base & (HD - 1);
    float4 o4 = *(const float4*)&X[base];
    float o[4] = {o4.x, o4.y, o4.z, o4.w};
    char r[4];
    #pragma unroll
    for (int j = 0; j < 4; j++) {
        int cj = c + j;
        float m = meanI[cj];
        float v = gamma[cj] * ((o[j] - m) * invI[cj]) + beta[cj];
        r[j] = (char)((v > 0.f) ? 1 : ((v < 0.f) ? -1 : 0));
        if (fabsf(o[j] - m) < TAU) flag[cj] = 1;
    }
    *(char4*)&A[base] = make_char4(r[0], r[1], r[2], r[3]);
}
__global__ void build_list(const int* __restrict__ flag, int* __restrict__ list,
                           int* __restrict__ cnt) {
    __shared__ int sflag[HD];
    int tid = threadIdx.x;
    for (int i = tid; i < HD; i += 256) sflag[i] = flag[i];
    __syncthreads();
    if (tid == 0) {
        int c = 0;
        for (int i = 0; i < HD; i++)
            if (sflag[i] && c < FIXCAP) list[c++] = i;
        cnt[0] = c;
    }
}

// ---------------- exact recompute of flagged columns (reference-order FMA chain) --------
// 64 cols x 128 rows per block: halves redundant x traffic vs 32-col version.
#define XRS 132
#define WRS 132
#define F1ROWS 128
#define F1COLS 64
#define FIX1_SMEM (F1ROWS * XRS * 4 + F1COLS * WRS)

__global__ __launch_bounds__(256) void fix1(
    const float* __restrict__ X, const int8_t* __restrict__ S1,
    const float* __restrict__ b1, const int* __restrict__ list,
    const int* __restrict__ cnt, float* __restrict__ fixBuf)
{
    int g = blockIdx.x, rb = blockIdx.y;
    int count = cnt[0];
    if (g * F1COLS >= count) return;

    extern __shared__ __align__(16) char sraw[];
    float* xbuf = (float*)sraw;                             // [128][XRS]
    int8_t* wbuf = (int8_t*)(xbuf + F1ROWS * XRS);          // [64][WRS]
    __shared__ int cols[F1COLS];

    int tid = threadIdx.x;
    int mycol = tid & 63, rowgrp = tid >> 6;                // 4 rowgrps x 32 rows
    if (tid < F1COLS) {
        int slot = g * F1COLS + tid;
        cols[tid] = (slot < count) ? list[slot] : list[count - 1];
    }
    __syncthreads();
    int col = cols[mycol];

    float acc[32];
    #pragma unroll
    for (int j = 0; j < 32; j++) acc[j] = 0.f;
    int rbase = rb * F1ROWS;

    for (int kc = 0; kc < K1D; kc += 128) {
        __syncthreads();
        #pragma unroll 8
        for (int t = 0; t < 64; t++) {                      // 128*128/256
            int id = tid + t * 256;
            int r = id >> 7, k = id & 127;
            xbuf[r * XRS + k] = X[(size_t)(rbase + r) * K1D + kc + k];
        }
        #pragma unroll
        for (int t = 0; t < 32; t++) {                      // 64*128/256
            int e = tid + t * 256;
            int c = e >> 7, k = e & 127;
            wbuf[c * WRS + k] = S1[(size_t)cols[c] * K1D + kc + k];
        }
        __syncthreads();
        int rb32 = rowgrp * 32;
        #pragma unroll 2
        for (int k = 0; k < 128; k++) {
            float w = (float)wbuf[mycol * WRS + k];
            #pragma unroll
            for (int j = 0; j < 32; j++)
                acc[j] = fmaf(xbuf[(rb32 + j) * XRS + k], w, acc[j]);
        }
    }

    int slot = g * F1COLS + mycol;
    if (slot < count) {
        float bb = b1[col];
        #pragma unroll
        for (int j = 0; j < 32; j++) {
            int row = rbase + rowgrp * 32 + j;
            fixBuf[(size_t)row * FIXCAP + slot] = acc[j] + bb;
        }
    }
}

__global__ __launch_bounds__(256) void fix2(
    const float* __restrict__ fixBuf, const int* __restrict__ list,
    const int* __restrict__ cnt, const float* __restrict__ invI,
    const float* __restrict__ gamma, const float* __restrict__ beta,
    int8_t* __restrict__ A)
{
    int s = blockIdx.x;
    if (s >= cnt[0]) return;
    int col = list[s];
    __shared__ float buf[MB];
    __shared__ float mu_s;
    int tid = threadIdx.x;
    for (int r = tid; r < MB; r += 256) buf[r] = fixBuf[(size_t)r * FIXCAP + s];
    __syncthreads();
    if (tid == 0) {
        float ssum = 0.f;
        for (int r = 0; r < MB; r++) ssum += buf[r];
        mu_s = ssum / (float)MB;
    }
    __syncthreads();
    float mu = mu_s, iv = invI[col], gg = gamma[col], bb = beta[col];
    for (int r = tid; r < MB; r += 256) {
        float v = gg * ((buf[r] - mu) * iv) + bb;
        A[(size_t)r * HD + col] = (int8_t)((v > 0.f) ? 1 : ((v < 0.f) ? -1 : 0));
    }
}

// ---------------- exact integer stats finalize + sign (layers 2, 3) ----------------
__global__ void clear_int(int* s, unsigned long long* q, int n) {
    int i = blockIdx.x * 256 + threadIdx.x;
    if (i < n) { s[i] = 0; q[i] = 0ull; }
}
__global__ void finalize_int(const int* __restrict__ S, const unsigned long long* __restrict__ Q,
                             float* __restrict__ invO, int NC) {
    int c = blockIdx.x * 256 + threadIdx.x;
    if (c >= NC) return;
    double mean = (double)S[c] / MB;
    double var = (double)Q[c] / MB - mean * mean;
    if (var < 0) var = 0;
    invO[c] = (float)rsqrt(var + 1e-5);
}
__global__ void bn_sign_exact8(const int16_t* __restrict__ X, int8_t* __restrict__ A,
                               const int* __restrict__ S, const float* __restrict__ invI,
                               const float* __restrict__ gamma, const float* __restrict__ beta) {
    int idx = blockIdx.x * 256 + threadIdx.x;
    int base = idx * 8;
    int c = base & (HD - 1);
    short vals[8];
    *(uint4*)vals = *(const uint4*)&X[base];
    char r[8];
    #pragma unroll
    for (int j = 0; j < 8; j++) {
        int cj = c + j;
        long long t = (long long)vals[j] * MB - (long long)S[cj];
        float v = gamma[cj] * ((float)t * (invI[cj] * (1.f / MB))) + beta[cj];
        r[j] = (char)((v > 0.f) ? 1 : ((v < 0.f) ? -1 : 0));
    }
    *(uint2*)&A[base] = *(uint2*)r;
}
__global__ void bn_final_s16(const int16_t* __restrict__ X, float* __restrict__ out,
                             const int* __restrict__ S, const float* __restrict__ invI,
                             const float* __restrict__ gamma, const float* __restrict__ beta,
                             int total, int NC, int ldc) {
    int idx = blockIdx.x * 256 + threadIdx.x;
    if (idx >= total) return;
    int r = idx / NC, c = idx % NC;
    float o = (float)X[(size_t)r * ldc + c];
    float mean = (float)((double)S[c] / MB);
    out[idx] = gamma[c] * ((o - mean) * invI[c]) + beta[c];
}

// ---------------- launch ----------------
extern "C" void kernel_launch(void* const* d_in, const int* in_sizes, int n_in,
                              void* d_out, int out_size) {
    const float* x   = (const float*)d_in[0];
    const float* W1  = (const float*)d_in[1];
    const float* b1  = (const float*)d_in[2];
    const float* g1  = (const float*)d_in[3];
    const float* be1 = (const float*)d_in[4];
    const float* W2  = (const float*)d_in[5];
    const float* b2  = (const float*)d_in[6];
    const float* g2  = (const float*)d_in[7];
    const float* be2 = (const float*)d_in[8];
    const float* W3  = (const float*)d_in[9];
    const float* b3  = (const float*)d_in[10];
    const float* g3  = (const float*)d_in[11];
    const float* be3 = (const float*)d_in[12];
    float* out = (float*)d_out;

    int8_t *S1i, *S2i, *S3i, *A8x, *A8;
    float *lin, *fS, *fQ, *mean, *inv, *fixBuf;
    int *flag, *list, *cntp, *isum;
    unsigned long long* isq;
    cudaGetSymbolAddress((void**)&S1i, g_S1i);
    cudaGetSymbolAddress((void**)&S2i, g_S2i);
    cudaGetSymbolAddress((void**)&S3i, g_S3i);
    cudaGetSymbolAddress((void**)&A8x, g_A8x);
    cudaGetSymbolAddress((void**)&A8, g_A8);
    cudaGetSymbolAddress((void**)&lin, g_lin);
    cudaGetSymbolAddress((void**)&fS, g_fS);
    cudaGetSymbolAddress((void**)&fQ, g_fQ);
    cudaGetSymbolAddress((void**)&mean, g_mean);
    cudaGetSymbolAddress((void**)&inv, g_inv);
    cudaGetSymbolAddress((void**)&fixBuf, g_fix);
    cudaGetSymbolAddress((void**)&flag, g_colFlag);
    cudaGetSymbolAddress((void**)&list, g_list);
    cudaGetSymbolAddress((void**)&cntp, g_fixCount);
    cudaGetSymbolAddress((void**)&isum, g_isum);
    cudaGetSymbolAddress((void**)&isq, g_isq);
    int16_t* lin16 = (int16_t*)lin;

    cudaFuncSetAttribute(gemm_s8, cudaFuncAttributeMaxDynamicSharedMemorySize, ISMEM_BYTES);
    cudaFuncSetAttribute(gemm_s8_l1, cudaFuncAttributeMaxDynamicSharedMemorySize, L1SMEM_BYTES);
    cudaFuncSetAttribute(fix1, cudaFuncAttributeMaxDynamicSharedMemorySize, FIX1_SMEM);

    // prep
    prep_w_s8<<<HD, 256>>>(W1, S1i, K1D);
    prep_w_s8<<<HD, 256>>>(W2, S2i, HD);
    prep_w_s8<<<OD, 256>>>(W3, S3i, HD);
    quant_x<<<(MB * K1D + 255) / 256, 256>>>(x, A8x, MB * K1D);

    // layer 1: 3-plane s8 IMMA GEMM w/ fused fp32 stats + exact fix of boundary columns
    clear_f<<<(HD + 255) / 256, 256>>>(fS, fQ, HD);
    gemm_s8_l1<<<dim3(HD / L1BN, MB / IBM), 256, L1SMEM_BYTES>>>(A8x, S1i, lin, b1, HD, fS, fQ);
    l1_reduce<<<HD / 256, 256>>>(fS, fQ, mean, inv);
    clear_flags<<<(HD + 255) / 256, 256>>>(flag, cntp);
    bn_sign_flag<<<(MB * HD / 4) / 256, 256>>>(lin, A8, mean, inv, g1, be1, flag);
    build_list<<<1, 256>>>(flag, list, cntp);
    fix1<<<dim3(FIXCAP / F1COLS, MB / F1ROWS), 256, FIX1_SMEM>>>(x, S1i, b1, list, cntp, fixBuf);
    fix2<<<FIXCAP, 256>>>(fixBuf, list, cntp, inv, g1, be1, A8);

    // layer 2: s8 IMMA GEMM w/ fused exact int stats, s16 out
    clear_int<<<(HD + 255) / 256, 256>>>(isum, isq, HD);
    gemm_s8<<<dim3(HD / IBN, MB / IBM), 256, ISMEM_BYTES>>>(A8, S2i, lin16, isum, isq,
                                                            MB, HD, HD, HD);
    finalize_int<<<HD / 256, 256>>>(isum, isq, inv, HD);
    bn_sign_exact8<<<(MB * HD / 8) / 256, 256>>>(lin16, A8, isum, inv, g2, be2);

    // layer 3: N=10 (ldc=16), s8 IMMA w/ fused stats
    clear_int<<<1, 256>>>(isum, isq, 16);
    gemm_s8<<<dim3(1, MB / IBM), 256, ISMEM_BYTES>>>(A8, S3i, lin16, isum, isq,
                                                     MB, OD, HD, 16);
    finalize_int<<<1, 32>>>(isum, isq, inv, OD);
    bn_final_s16<<<(MB * OD + 255) / 256, 256>>>(lin16, out, isum, inv, g3, be3,
                                                 MB * OD, OD, 16);
}

// round 15
// speedup vs baseline: 1.1084x; 1.1084x over previous
#include <cuda_runtime.h>
#include <cuda_bf16.h>
#include <cstdint>

// ---------------- scratch (device globals: allocation-free) ----------------
#define MB   8192
#define K1D  1024
#define HD   4096
#define OD   10
#define FIXCAP 1024
#define TAU  5e-4f

__device__ int8_t        g_S1i[(size_t)HD * K1D];      // sign(W1) s8
__device__ int8_t        g_S2i[(size_t)HD * HD];       // sign(W2) s8
__device__ int8_t        g_S3i[(size_t)OD * HD];       // sign(W3) s8
__device__ int8_t        g_A8x[(size_t)MB * 3 * K1D];  // x as 3 int8 digit planes
__device__ int8_t        g_A8[(size_t)MB * HD];        // +/-1 activations (s8)
__device__ float         g_lin[(size_t)MB * HD];       // L1 float out; L2/L3 s16 view
__device__ float         g_partS[32 * HD];
__device__ float         g_partQ[32 * HD];
__device__ float         g_mean[HD];
__device__ float         g_inv [HD];
__device__ int           g_colFlag[HD];
__device__ int           g_list[FIXCAP];
__device__ int           g_fixCount[1];
__device__ float         g_fix[(size_t)MB * FIXCAP];   // exact outputs for flagged columns
__device__ int                g_isum[HD];
__device__ unsigned long long g_isq [HD];

// ---------------- weight binarization (s8) ----------------
__global__ void prep_w_s8(const float* __restrict__ W, int8_t* __restrict__ S, int I) {
    int o = blockIdx.x;
    const float* w = W + (size_t)o * I;
    __shared__ float red[256];
    float s = 0.f;
    for (int i = threadIdx.x; i < I; i += 256) s += fabsf(w[i]);
    red[threadIdx.x] = s; __syncthreads();
    for (int k = 128; k > 0; k >>= 1) {
        if (threadIdx.x < k) red[threadIdx.x] += red[threadIdx.x + k];
        __syncthreads();
    }
    int mask = (red[0] != 0.f) ? 1 : 0;
    for (int i = threadIdx.x; i < I; i += 256) {
        float v = w[i];
        int sg = (v > 0.f) ? 1 : ((v < 0.f) ? -1 : 0);
        S[(size_t)o * I + i] = (int8_t)(sg * mask);
    }
}

// ---------------- exact 3-plane int8 fixed-point split of x ----------------
__global__ void quant_x(const float* __restrict__ x, int8_t* __restrict__ Aq, int total) {
    int idx = blockIdx.x * 256 + threadIdx.x;
    if (idx >= total) return;
    int r = idx / K1D, k = idx % K1D;
    float v = x[idx];
    float d0 = rintf(v * 16.f);
    float r1 = v - d0 * 0.0625f;
    float d1 = rintf(r1 * 2048.f);
    float r2 = r1 - d1 * 4.8828125e-4f;
    float d2 = rintf(r2 * 262144.f);
    size_t base = (size_t)r * (3 * K1D) + k;
    Aq[base]            = (int8_t)(int)d0;
    Aq[base + K1D]      = (int8_t)(int)d1;
    Aq[base + 2 * K1D]  = (int8_t)(int)d2;
}

// ---------------- PTX helpers ----------------
static __device__ __forceinline__ uint32_t smem_u32(const void* p) {
    return (uint32_t)__cvta_generic_to_shared(p);
}
static __device__ __forceinline__ void cp_async16p(void* smem, const void* gmem, bool pred) {
    uint32_t s = smem_u32(smem);
    int sz = pred ? 16 : 0;
    asm volatile("cp.async.cg.shared.global [%0], [%1], 16, %2;\n" :: "r"(s), "l"(gmem), "r"(sz));
}
static __device__ __forceinline__ void ldsm_x4(uint32_t& r0, uint32_t& r1, uint32_t& r2,
                                               uint32_t& r3, uint32_t addr) {
    asm volatile("ldmatrix.sync.aligned.m8n8.x4.shared.b16 {%0,%1,%2,%3}, [%4];\n"
                 : "=r"(r0), "=r"(r1), "=r"(r2), "=r"(r3) : "r"(addr));
}
static __device__ __forceinline__ void mma_s8(int* c, uint32_t a0, uint32_t a1, uint32_t a2,
                                              uint32_t a3, uint32_t b0, uint32_t b1) {
    asm volatile("mma.sync.aligned.m16n8k32.row.col.s32.s8.s8.s32 "
                 "{%0,%1,%2,%3}, {%4,%5,%6,%7}, {%8,%9}, {%0,%1,%2,%3};\n"
                 : "+r"(c[0]), "+r"(c[1]), "+r"(c[2]), "+r"(c[3])
                 : "r"(a0), "r"(a1), "r"(a2), "r"(a3), "r"(b0), "r"(b1));
}

// ================= s8 IMMA GEMM common tile config ================
#define IBM 128
#define IBN 128
#define IBK 64
#define STAGES 3
#define ISAST 80
#define ISTG (IBM * ISAST)
#define ISMEM_BYTES (STAGES * 2 * ISTG)

// ====== s8 IMMA GEMM (layers 2, 3): raw s16 acc out + fused exact int col-stats ======
__global__ __launch_bounds__(256) void gemm_s8(
    const int8_t* __restrict__ A, const int8_t* __restrict__ B,
    int16_t* __restrict__ C16, int* __restrict__ gS, unsigned long long* __restrict__ gQ,
    int M, int N, int K, int ldc)
{
    extern __shared__ __align__(16) char smem_raw[];
    char* sA = smem_raw;
    char* sB = smem_raw + STAGES * ISTG;

    int tid = threadIdx.x;
    int mBase = blockIdx.y * IBM;
    int nBase = blockIdx.x * IBN;
    int warp = tid >> 5, lane = tid & 31;
    int wMB = (warp & 1) * 64;
    int wNB = (warp >> 1) * 32;
    int q = lane >> 2;

    int aRow = ((lane >> 3) & 1) * 8 + (lane & 7);
    int aCol = (lane >> 4) * 16;
    int bRow = (lane >> 4) * 8 + (lane & 7);
    int bCol = ((lane >> 3) & 1) * 16;

    int acc[4][4][4];
    #pragma unroll
    for (int i = 0; i < 4; i++)
        #pragma unroll
        for (int j = 0; j < 4; j++)
            #pragma unroll
            for (int r = 0; r < 4; r++) acc[i][j][r] = 0;

    int ktiles = K / IBK;

    #pragma unroll
    for (int st = 0; st < STAGES - 1; st++) {
        int k0 = st * IBK;
        #pragma unroll
        for (int i = 0; i < 2; i++) {
            int id = tid + i * 256;
            int r = id >> 2, c = id & 3;
            cp_async16p(sA + st * ISTG + r * ISAST + c * 16,
                        A + (size_t)(mBase + r) * K + k0 + c * 16, true);
            bool pb = (nBase + r) < N;
            cp_async16p(sB + st * ISTG + r * ISAST + c * 16,
                        B + (size_t)(nBase + r) * K + k0 + c * 16, pb);
        }
        asm volatile("cp.async.commit_group;\n");
    }

    for (int kt = 0; kt < ktiles; kt++) {
        asm volatile("cp.async.wait_group %0;\n" :: "n"(STAGES - 2));
        __syncthreads();

        int nt = kt + STAGES - 1;
        if (nt < ktiles) {
            int st = nt % STAGES;
            int k0 = nt * IBK;
            #pragma unroll
            for (int i = 0; i < 2; i++) {
                int id = tid + i * 256;
                int r = id >> 2, c = id & 3;
                cp_async16p(sA + st * ISTG + r * ISAST + c * 16,
                            A + (size_t)(mBase + r) * K + k0 + c * 16, true);
                bool pb = (nBase + r) < N;
                cp_async16p(sB + st * ISTG + r * ISAST + c * 16,
                            B + (size_t)(nBase + r) * K + k0 + c * 16, pb);
            }
        }
        asm volatile("cp.async.commit_group;\n");

        int stage = kt % STAGES;
        const char* tA = sA + stage * ISTG;
        const char* tB = sB + stage * ISTG;

        #pragma unroll
        for (int kk = 0; kk < 2; kk++) {
            int kb = kk * 32;
            uint32_t af[4][4], bf[4][2];
            #pragma unroll
            for (int im = 0; im < 4; im++) {
                uint32_t addr = smem_u32(tA + (wMB + im * 16 + aRow) * ISAST + kb + aCol);
                ldsm_x4(af[im][0], af[im][1], af[im][2], af[im][3], addr);
            }
            #pragma unroll
            for (int p = 0; p < 2; p++) {
                uint32_t addr = smem_u32(tB + (wNB + p * 16 + bRow) * ISAST + kb + bCol);
                uint32_t r0, r1, r2, r3;
                ldsm_x4(r0, r1, r2, r3, addr);
                bf[2 * p][0] = r0; bf[2 * p][1] = r1;
                bf[2 * p + 1][0] = r2; bf[2 * p + 1][1] = r3;
            }
            #pragma unroll
            for (int im = 0; im < 4; im++)
                #pragma unroll
                for (int jn = 0; jn < 4; jn++)
                    mma_s8(acc[im][jn], af[im][0], af[im][1], af[im][2], af[im][3],
                           bf[jn][0], bf[jn][1]);
        }
    }

    // ---- store raw s16 acc ----
    #pragma unroll
    for (int im = 0; im < 4; im++) {
        int mrow = mBase + wMB + im * 16 + q;
        #pragma unroll
        for (int jn = 0; jn < 4; jn++) {
            int ncol = nBase + wNB + jn * 8 + (lane & 3) * 2;
            #pragma unroll
            for (int rg = 0; rg < 2; rg++) {
                int row = mrow + rg * 8;
                if (ncol < N) {
                    short2 v;
                    v.x = (short)acc[im][jn][rg * 2 + 0];
                    v.y = (short)acc[im][jn][rg * 2 + 1];
                    *(short2*)&C16[(size_t)row * ldc + ncol] = v;
                }
            }
        }
    }

    // ---- fused exact integer column stats (deterministic: integer atomics) ----
    __syncthreads();
    int* sS = (int*)smem_raw;
    unsigned long long* sQ = (unsigned long long*)(smem_raw + 512);
    for (int i = tid; i < 128; i += 256) { sS[i] = 0; sQ[i] = 0ull; }
    __syncthreads();
    #pragma unroll
    for (int jn = 0; jn < 4; jn++) {
        int cl = wNB + jn * 8 + (lane & 3) * 2;
        int s0 = 0, s1 = 0; int q0 = 0, q1 = 0;
        #pragma unroll
        for (int im = 0; im < 4; im++)
            #pragma unroll
            for (int rg = 0; rg < 2; rg++) {
                int v0 = acc[im][jn][rg * 2 + 0];
                int v1 = acc[im][jn][rg * 2 + 1];
                s0 += v0; q0 += v0 * v0;
                s1 += v1; q1 += v1 * v1;
            }
        atomicAdd(&sS[cl], s0);
        atomicAdd(&sQ[cl], (unsigned long long)(long long)q0);
        atomicAdd(&sS[cl + 1], s1);
        atomicAdd(&sQ[cl + 1], (unsigned long long)(long long)q1);
    }
    __syncthreads();
    for (int c = tid; c < 128; c += 256) {
        if (nBase + c < N) {
            atomicAdd(&gS[nBase + c], sS[c]);
            atomicAdd(&gQ[nBase + c], sQ[c]);
        }
    }
}

// ====== s8 IMMA GEMM, layer 1: 3 digit planes over the SAME weight matrix ======
#define L1BN 64
#define L1BSTG (L1BN * ISAST)
#define L1STG (ISTG + L1BSTG)
#define L1SMEM_BYTES (STAGES * L1STG)
#define L1TILES 48    // 3 planes * (K1D/IBK)

__global__ __launch_bounds__(256, 2) void gemm_s8_l1(
    const int8_t* __restrict__ A, const int8_t* __restrict__ B,
    float* __restrict__ C, const float* __restrict__ bias, int ldc)
{
    extern __shared__ __align__(16) char smem_raw[];
    char* sA = smem_raw;
    char* sB = smem_raw + STAGES * ISTG;

    int tid = threadIdx.x;
    int mBase = blockIdx.y * IBM;
    int nBase = blockIdx.x * L1BN;
    int warp = tid >> 5, lane = tid & 31;
    int wMB = (warp & 3) * 32;
    int wNB = (warp >> 2) * 32;
    int q = lane >> 2;

    int aRow = ((lane >> 3) & 1) * 8 + (lane & 7);
    int aCol = (lane >> 4) * 16;
    int bRow = (lane >> 4) * 8 + (lane & 7);
    int bCol = ((lane >> 3) & 1) * 16;

    const float scl[3] = {0.0625f, 4.8828125e-4f, 3.814697265625e-6f};

    int acc[2][4][4];
    float facc[2][4][4];
    #pragma unroll
    for (int i = 0; i < 2; i++)
        #pragma unroll
        for (int j = 0; j < 4; j++)
            #pragma unroll
            for (int r = 0; r < 4; r++) { acc[i][j][r] = 0; facc[i][j][r] = 0.f; }

    #pragma unroll
    for (int st = 0; st < STAGES - 1; st++) {
        int ka = st * IBK;
        int kb = (st & 15) * IBK;
        #pragma unroll
        for (int i = 0; i < 2; i++) {
            int id = tid + i * 256;
            int r = id >> 2, c = id & 3;
            cp_async16p(sA + st * ISTG + r * ISAST + c * 16,
                        A + (size_t)(mBase + r) * (3 * K1D) + ka + c * 16, true);
        }
        {
            int r = tid >> 2, c = tid & 3;
            cp_async16p(sB + st * L1BSTG + r * ISAST + c * 16,
                        B + (size_t)(nBase + r) * K1D + kb + c * 16, true);
        }
        asm volatile("cp.async.commit_group;\n");
    }

    for (int kt = 0; kt < L1TILES; kt++) {
        asm volatile("cp.async.wait_group %0;\n" :: "n"(STAGES - 2));
        __syncthreads();

        int nt = kt + STAGES - 1;
        if (nt < L1TILES) {
            int st = nt % STAGES;
            int ka = nt * IBK;
            int kb = (nt & 15) * IBK;
            #pragma unroll
            for (int i = 0; i < 2; i++) {
                int id = tid + i * 256;
                int r = id >> 2, c = id & 3;
                cp_async16p(sA + st * ISTG + r * ISAST + c * 16,
                            A + (size_t)(mBase + r) * (3 * K1D) + ka + c * 16, true);
            }
            {
                int r = tid >> 2, c = tid & 3;
                cp_async16p(sB + st * L1BSTG + r * ISAST + c * 16,
                            B + (size_t)(nBase + r) * K1D + kb + c * 16, true);
            }
        }
        asm volatile("cp.async.commit_group;\n");

        int stage = kt % STAGES;
        const char* tA = sA + stage * ISTG;
        const char* tB = sB + stage * L1BSTG;

        #pragma unroll
        for (int kk = 0; kk < 2; kk++) {
            int kb = kk * 32;
            uint32_t af[2][4], bf[4][2];
            #pragma unroll
            for (int im = 0; im < 2; im++) {
                uint32_t addr = smem_u32(tA + (wMB + im * 16 + aRow) * ISAST + kb + aCol);
                ldsm_x4(af[im][0], af[im][1], af[im][2], af[im][3], addr);
            }
            #pragma unroll
            for (int p = 0; p < 2; p++) {
                uint32_t addr = smem_u32(tB + (wNB + p * 16 + bRow) * ISAST + kb + bCol);
                uint32_t r0, r1, r2, r3;
                ldsm_x4(r0, r1, r2, r3, addr);
                bf[2 * p][0] = r0; bf[2 * p][1] = r1;
                bf[2 * p + 1][0] = r2; bf[2 * p + 1][1] = r3;
            }
            #pragma unroll
            for (int im = 0; im < 2; im++)
                #pragma unroll
                for (int jn = 0; jn < 4; jn++)
                    mma_s8(acc[im][jn], af[im][0], af[im][1], af[im][2], af[im][3],
                           bf[jn][0], bf[jn][1]);
        }

        if ((kt & 15) == 15) {
            float s = scl[kt >> 4];
            #pragma unroll
            for (int im = 0; im < 2; im++)
                #pragma unroll
                for (int jn = 0; jn < 4; jn++)
                    #pragma unroll
                    for (int r = 0; r < 4; r++) {
                        facc[im][jn][r] = fmaf(s, (float)acc[im][jn][r], facc[im][jn][r]);
                        acc[im][jn][r] = 0;
                    }
        }
    }

    #pragma unroll
    for (int im = 0; im < 2; im++) {
        int mrow = mBase + wMB + im * 16 + q;
        #pragma unroll
        for (int jn = 0; jn < 4; jn++) {
            int ncol = nBase + wNB + jn * 8 + (lane & 3) * 2;
            #pragma unroll
            for (int rg = 0; rg < 2; rg++) {
                int row = mrow + rg * 8;
                C[(size_t)row * ldc + ncol]     = facc[im][jn][rg * 2 + 0] + bias[ncol];
                C[(size_t)row * ldc + ncol + 1] = facc[im][jn][rg * 2 + 1] + bias[ncol + 1];
            }
        }
    }
}

// ---------------- layer-1 stats: parallel partials ----------------
__global__ void l1_part(const float* __restrict__ X, float* __restrict__ pS,
                        float* __restrict__ pQ) {
    int col = blockIdx.x * 256 + threadIdx.x;
    int by = blockIdx.y;
    float s = 0.f, qq = 0.f;
    for (int r = by * 256; r < (by + 1) * 256; r++) {
        float v = X[(size_t)r * HD + col];
        s += v; qq = fmaf(v, v, qq);
    }
    pS[by * HD + col] = s;
    pQ[by * HD + col] = qq;
}
__global__ void l1_reduce(const float* __restrict__ pS, const float* __restrict__ pQ,
                          float* __restrict__ meanO, float* __restrict__ invO) {
    int c = blockIdx.x * 256 + threadIdx.x;
    float s = 0.f, qq = 0.f;
    for (int b = 0; b < 32; b++) { s += pS[b * HD + c]; qq += pQ[b * HD + c]; }
    float mu = s * (1.f / MB);
    float var = fmaxf(qq * (1.f / MB) - mu * mu, 0.f);
    meanO[c] = mu;
    invO[c] = rsqrtf(var + 1e-5f);
}

// ---------------- approx sign (s8 out) + boundary-column flagging, float4 ----------------
__global__ void clear_flags(int* __restrict__ flag, int* __restrict__ cnt) {
    int i = blockIdx.x * 256 + threadIdx.x;
    if (i < HD) flag[i] = 0;
    if (i == 0) cnt[0] = 0;
}
__global__ void bn_sign_flag(const float* __restrict__ X, int8_t* __restrict__ A,
                             const float* __restrict__ meanI, const float* __restrict__ invI,
                             const float* __restrict__ gamma, const float* __restrict__ beta,
                             int* __restrict__ flag) {
    int idx = blockIdx.x * 256 + threadIdx.x;
    int base = idx * 4;
    int c = base & (HD - 1);
    float4 o4 = *(const float4*)&X[base];
    float o[4] = {o4.x, o4.y, o4.z, o4.w};
    char r[4];
    #pragma unroll
    for (int j = 0; j < 4; j++) {
        int cj = c + j;
        float m = meanI[cj];
        float v = gamma[cj] * ((o[j] - m) * invI[cj]) + beta[cj];
        r[j] = (char)((v > 0.f) ? 1 : ((v < 0.f) ? -1 : 0));
        if (fabsf(o[j] - m) < TAU) flag[cj] = 1;
    }
    *(char4*)&A[base] = make_char4(r[0], r[1], r[2], r[3]);
}
__global__ void build_list(const int* __restrict__ flag, int* __restrict__ list,
                           int* __restrict__ cnt) {
    __shared__ int sflag[HD];
    int tid = threadIdx.x;
    for (int i = tid; i < HD; i += 256) sflag[i] = flag[i];
    __syncthreads();
    if (tid == 0) {
        int c = 0;
        for (int i = 0; i < HD; i++)
            if (sflag[i] && c < FIXCAP) list[c++] = i;
        cnt[0] = c;
    }
}

// ---------------- exact recompute of flagged columns (reference-order FMA chain) --------
// 64 cols x 128 rows per block: halves redundant x traffic vs 32-col version.
#define XRS 132
#define WRS 132
#define F1ROWS 128
#define F1COLS 64
#define FIX1_SMEM (F1ROWS * XRS * 4 + F1COLS * WRS)

__global__ __launch_bounds__(256) void fix1(
    const float* __restrict__ X, const int8_t* __restrict__ S1,
    const float* __restrict__ b1, const int* __restrict__ list,
    const int* __restrict__ cnt, float* __restrict__ fixBuf)
{
    int g = blockIdx.x, rb = blockIdx.y;
    int count = cnt[0];
    if (g * F1COLS >= count) return;

    extern __shared__ __align__(16) char sraw[];
    float* xbuf = (float*)sraw;                             // [128][XRS]
    int8_t* wbuf = (int8_t*)(xbuf + F1ROWS * XRS);          // [64][WRS]
    __shared__ int cols[F1COLS];

    int tid = threadIdx.x;
    int mycol = tid & 63, rowgrp = tid >> 6;                // 4 rowgrps x 32 rows
    if (tid < F1COLS) {
        int slot = g * F1COLS + tid;
        cols[tid] = (slot < count) ? list[slot] : list[count - 1];
    }
    __syncthreads();
    int col = cols[mycol];

    float acc[32];
    #pragma unroll
    for (int j = 0; j < 32; j++) acc[j] = 0.f;
    int rbase = rb * F1ROWS;

    for (int kc = 0; kc < K1D; kc += 128) {
        __syncthreads();
        #pragma unroll 8
        for (int t = 0; t < 64; t++) {                      // 128*128/256
            int id = tid + t * 256;
            int r = id >> 7, k = id & 127;
            xbuf[r * XRS + k] = X[(size_t)(rbase + r) * K1D + kc + k];
        }
        #pragma unroll
        for (int t = 0; t < 32; t++) {                      // 64*128/256
            int e = tid + t * 256;
            int c = e >> 7, k = e & 127;
            wbuf[c * WRS + k] = S1[(size_t)cols[c] * K1D + kc + k];
        }
        __syncthreads();
        int rb32 = rowgrp * 32;
        #pragma unroll 2
        for (int k = 0; k < 128; k++) {
            float w = (float)wbuf[mycol * WRS + k];
            #pragma unroll
            for (int j = 0; j < 32; j++)
                acc[j] = fmaf(xbuf[(rb32 + j) * XRS + k], w, acc[j]);
        }
    }

    int slot = g * F1COLS + mycol;
    if (slot < count) {
        float bb = b1[col];
        #pragma unroll
        for (int j = 0; j < 32; j++) {
            int row = rbase + rowgrp * 32 + j;
            fixBuf[(size_t)row * FIXCAP + slot] = acc[j] + bb;
        }
    }
}

__global__ __launch_bounds__(256) void fix2(
    const float* __restrict__ fixBuf, const int* __restrict__ list,
    const int* __restrict__ cnt, const float* __restrict__ invI,
    const float* __restrict__ gamma, const float* __restrict__ beta,
    int8_t* __restrict__ A)
{
    int s = blockIdx.x;
    if (s >= cnt[0]) return;
    int col = list[s];
    __shared__ float buf[MB];
    __shared__ float mu_s;
    int tid = threadIdx.x;
    for (int r = tid; r < MB; r += 256) buf[r] = fixBuf[(size_t)r * FIXCAP + s];
    __syncthreads();
    if (tid == 0) {
        float ssum = 0.f;
        for (int r = 0; r < MB; r++) ssum += buf[r];
        mu_s = ssum / (float)MB;
    }
    __syncthreads();
    float mu = mu_s, iv = invI[col], gg = gamma[col], bb = beta[col];
    for (int r = tid; r < MB; r += 256) {
        float v = gg * ((buf[r] - mu) * iv) + bb;
        A[(size_t)r * HD + col] = (int8_t)((v > 0.f) ? 1 : ((v < 0.f) ? -1 : 0));
    }
}

// ---------------- exact integer stats finalize + sign (layers 2, 3) ----------------
__global__ void clear_int(int* s, unsigned long long* q, int n) {
    int i = blockIdx.x * 256 + threadIdx.x;
    if (i < n) { s[i] = 0; q[i] = 0ull; }
}
__global__ void finalize_int(const int* __restrict__ S, const unsigned long long* __restrict__ Q,
                             float* __restrict__ invO, int NC) {
    int c = blockIdx.x * 256 + threadIdx.x;
    if (c >= NC) return;
    double mean = (double)S[c] / MB;
    double var = (double)Q[c] / MB - mean * mean;
    if (var < 0) var = 0;
    invO[c] = (float)rsqrt(var + 1e-5);
}
__global__ void bn_sign_exact8(const int16_t* __restrict__ X, int8_t* __restrict__ A,
                               const int* __restrict__ S, const float* __restrict__ invI,
                               const float* __restrict__ gamma, const float* __restrict__ beta) {
    int idx = blockIdx.x * 256 + threadIdx.x;
    int base = idx * 8;
    int c = base & (HD - 1);
    short vals[8];
    *(uint4*)vals = *(const uint4*)&X[base];
    char r[8];
    #pragma unroll
    for (int j = 0; j < 8; j++) {
        int cj = c + j;
        long long t = (long long)vals[j] * MB - (long long)S[cj];
        float v = gamma[cj] * ((float)t * (invI[cj] * (1.f / MB))) + beta[cj];
        r[j] = (char)((v > 0.f) ? 1 : ((v < 0.f) ? -1 : 0));
    }
    *(uint2*)&A[base] = *(uint2*)r;
}
__global__ void bn_final_s16(const int16_t* __restrict__ X, float* __restrict__ out,
                             const int* __restrict__ S, const float* __restrict__ invI,
                             const float* __restrict__ gamma, const float* __restrict__ beta,
                             int total, int NC, int ldc) {
    int idx = blockIdx.x * 256 + threadIdx.x;
    if (idx >= total) return;
    int r = idx / NC, c = idx % NC;
    float o = (float)X[(size_t)r * ldc + c];
    float mean = (float)((double)S[c] / MB);
    out[idx] = gamma[c] * ((o - mean) * invI[c]) + beta[c];
}

// ---------------- launch ----------------
extern "C" void kernel_launch(void* const* d_in, const int* in_sizes, int n_in,
                              void* d_out, int out_size) {
    const float* x   = (const float*)d_in[0];
    const float* W1  = (const float*)d_in[1];
    const float* b1  = (const float*)d_in[2];
    const float* g1  = (const float*)d_in[3];
    const float* be1 = (const float*)d_in[4];
    const float* W2  = (const float*)d_in[5];
    const float* b2  = (const float*)d_in[6];
    const float* g2  = (const float*)d_in[7];
    const float* be2 = (const float*)d_in[8];
    const float* W3  = (const float*)d_in[9];
    const float* b3  = (const float*)d_in[10];
    const float* g3  = (const float*)d_in[11];
    const float* be3 = (const float*)d_in[12];
    float* out = (float*)d_out;

    int8_t *S1i, *S2i, *S3i, *A8x, *A8;
    float *lin, *pS, *pQ, *mean, *inv, *fixBuf;
    int *flag, *list, *cntp, *isum;
    unsigned long long* isq;
    cudaGetSymbolAddress((void**)&S1i, g_S1i);
    cudaGetSymbolAddress((void**)&S2i, g_S2i);
    cudaGetSymbolAddress((void**)&S3i, g_S3i);
    cudaGetSymbolAddress((void**)&A8x, g_A8x);
    cudaGetSymbolAddress((void**)&A8, g_A8);
    cudaGetSymbolAddress((void**)&lin, g_lin);
    cudaGetSymbolAddress((void**)&pS, g_partS);
    cudaGetSymbolAddress((void**)&pQ, g_partQ);
    cudaGetSymbolAddress((void**)&mean, g_mean);
    cudaGetSymbolAddress((void**)&inv, g_inv);
    cudaGetSymbolAddress((void**)&fixBuf, g_fix);
    cudaGetSymbolAddress((void**)&flag, g_colFlag);
    cudaGetSymbolAddress((void**)&list, g_list);
    cudaGetSymbolAddress((void**)&cntp, g_fixCount);
    cudaGetSymbolAddress((void**)&isum, g_isum);
    cudaGetSymbolAddress((void**)&isq, g_isq);
    int16_t* lin16 = (int16_t*)lin;

    cudaFuncSetAttribute(gemm_s8, cudaFuncAttributeMaxDynamicSharedMemorySize, ISMEM_BYTES);
    cudaFuncSetAttribute(gemm_s8_l1, cudaFuncAttributeMaxDynamicSharedMemorySize, L1SMEM_BYTES);
    cudaFuncSetAttribute(fix1, cudaFuncAttributeMaxDynamicSharedMemorySize, FIX1_SMEM);

    // prep
    prep_w_s8<<<HD, 256>>>(W1, S1i, K1D);
    prep_w_s8<<<HD, 256>>>(W2, S2i, HD);
    prep_w_s8<<<OD, 256>>>(W3, S3i, HD);
    quant_x<<<(MB * K1D + 255) / 256, 256>>>(x, A8x, MB * K1D);

    // layer 1: 3-plane s8 IMMA GEMM (float out) + exact fix of boundary columns
    gemm_s8_l1<<<dim3(HD / L1BN, MB / IBM), 256, L1SMEM_BYTES>>>(A8x, S1i, lin, b1, HD);
    l1_part<<<dim3(HD / 256, 32), 256>>>(lin, pS, pQ);
    l1_reduce<<<HD / 256, 256>>>(pS, pQ, mean, inv);
    clear_flags<<<(HD + 255) / 256, 256>>>(flag, cntp);
    bn_sign_flag<<<(MB * HD / 4) / 256, 256>>>(lin, A8, mean, inv, g1, be1, flag);
    build_list<<<1, 256>>>(flag, list, cntp);
    fix1<<<dim3(FIXCAP / F1COLS, MB / F1ROWS), 256, FIX1_SMEM>>>(x, S1i, b1, list, cntp, fixBuf);
    fix2<<<FIXCAP, 256>>>(fixBuf, list, cntp, inv, g1, be1, A8);

    // layer 2: s8 IMMA GEMM w/ fused exact int stats, s16 out
    clear_int<<<(HD + 255) / 256, 256>>>(isum, isq, HD);
    gemm_s8<<<dim3(HD / IBN, MB / IBM), 256, ISMEM_BYTES>>>(A8, S2i, lin16, isum, isq,
                                                            MB, HD, HD, HD);
    finalize_int<<<HD / 256, 256>>>(isum, isq, inv, HD);
    bn_sign_exact8<<<(MB * HD / 8) / 256, 256>>>(lin16, A8, isum, inv, g2, be2);

    // layer 3: N=10 (ldc=16), s8 IMMA w/ fused stats
    clear_int<<<1, 256>>>(isum, isq, 16);
    gemm_s8<<<dim3(1, MB / IBM), 256, ISMEM_BYTES>>>(A8, S3i, lin16, isum, isq,
                                                     MB, OD, HD, 16);
    finalize_int<<<1, 32>>>(isum, isq, inv, OD);
    bn_final_s16<<<(MB * OD + 255) / 256, 256>>>(lin16, out, isum, inv, g3, be3,
                                                 MB * OD, OD, 16);
}